// round 15
// baseline (speedup 1.0000x reference)
#include <cuda_runtime.h>
#include <cstdint>
#include <cstddef>

#define B_ 32
#define S_ 4096
#define E_ 1024
#define H_ 16
#define D_ 64
#define NC 32            // chunks over s (128 rows each)
#define CH 128           // rows per chunk
#define RPB 16           // rows per batch
#define NBAT 8           // CH / RPB
#define SPR 1092         // spart row stride (floats): conflict-free
#define L2E 1.4426950408889634f

// ---------------- static scratch ----------------
__device__ float g_q[B_ * E_];
__device__ float g_qk[B_ * H_ * E_];
__device__ float g_ctxp[(size_t)NC * B_ * H_ * E_];   // unnormalized ctx per chunk (64MB)
__device__ float g_m[NC * B_ * H_];
__device__ float g_d[NC * B_ * H_];

typedef unsigned long long u64;

__device__ __forceinline__ u64 pack2(float x, float y) {
    u64 p;
    asm("mov.b64 %0, {%1, %2};" : "=l"(p) : "f"(x), "f"(y));
    return p;
}
__device__ __forceinline__ void unpack2(u64 p, float& x, float& y) {
    asm("mov.b64 {%0, %1}, %2;" : "=f"(x), "=f"(y) : "l"(p));
}
__device__ __forceinline__ u64 ffma2(u64 a, u64 b, u64 c) {
    u64 d;
    asm("fma.rn.f32x2 %0, %1, %2, %3;" : "=l"(d) : "l"(a), "l"(b), "l"(c));
    return d;
}
__device__ __forceinline__ u64 fmul2(u64 a, u64 b) {
    u64 d;
    asm("mul.rn.f32x2 %0, %1, %2;" : "=l"(d) : "l"(a), "l"(b));
    return d;
}
__device__ __forceinline__ void cp16(uint32_t dst_smem, const void* src) {
    asm volatile("cp.async.cg.shared.global [%0], [%1], 16;" :: "r"(dst_smem), "l"(src));
}
__device__ __forceinline__ void cp_commit() { asm volatile("cp.async.commit_group;"); }
template <int N>
__device__ __forceinline__ void cp_wait() { asm volatile("cp.async.wait_group %0;" :: "n"(N)); }

// ---------------- K1: q = seq1@Wq + bq  (1 b per block, ILP 16) ----------------
// grid (4 jt, 32 b) block 256
__global__ void k_qproj(const float* __restrict__ seq1, const float* __restrict__ Wq,
                        const float* __restrict__ bq) {
    int b = blockIdx.y;
    int j = blockIdx.x * 256 + threadIdx.x;
    __shared__ __align__(16) float s1[E_];
    ((float4*)s1)[threadIdx.x] = ((const float4*)(seq1 + (size_t)b * E_))[threadIdx.x];
    __syncthreads();
    float a[16];
#pragma unroll
    for (int i = 0; i < 16; i++) a[i] = 0.f;
#pragma unroll 2
    for (int e = 0; e < E_; e += 16) {
#pragma unroll
        for (int i = 0; i < 16; i++)
            a[i] = fmaf(s1[e + i], Wq[(size_t)(e + i) * E_ + j], a[i]);
    }
    float s = (((a[0] + a[1]) + (a[2] + a[3])) + ((a[4] + a[5]) + (a[6] + a[7]))) +
              (((a[8] + a[9]) + (a[10] + a[11])) + ((a[12] + a[13]) + (a[14] + a[15])));
    g_q[b * E_ + j] = s + bq[j];
}

// ---------------- K2: qk[b][h][e] = (Σ_d q[b][h*64+d]·Wk[e][h*64+d]) * 0.125 ----------------
// grid (16 h, 16 et) block 256
__global__ void k_qk(const float* __restrict__ Wk) {
    int h = blockIdx.x;
    int e = blockIdx.y * 64 + (threadIdx.x & 63);
    int bg = threadIdx.x >> 6;
    __shared__ __align__(16) float2 sq[B_][D_ / 2];
    for (int i = threadIdx.x; i < B_ * (D_ / 2); i += 256) {
        int b = i >> 5, dp = i & 31;
        sq[b][dp] = ((const float2*)(g_q + b * E_ + h * D_))[dp];
    }
    __syncthreads();
    float2 wk[D_ / 2];
    const float2* wrow = (const float2*)(Wk + (size_t)e * E_ + h * D_);
#pragma unroll
    for (int i = 0; i < D_ / 2; i++) wk[i] = wrow[i];
#pragma unroll
    for (int bb = 0; bb < 8; bb++) {
        int b = bg * 8 + bb;
        float ax = 0.f, ay = 0.f;
#pragma unroll
        for (int i = 0; i < D_ / 2; i++) {
            float2 qv = sq[b][i];
            ax = fmaf(wk[i].x, qv.x, ax);
            ay = fmaf(wk[i].y, qv.y, ay);
        }
        g_qk[(b * H_ + h) * E_ + e] = (ax + ay) * 0.125f;
    }
}

// ---------------- pad kernel (keeps ncu sample index on k_fused) ----------------
__global__ void k_pad() {}

// ---------------- K3: fused scores + online softmax + ctx ----------------
// grid (NC, B_) block 512
// Phase A thread: hg = tid&3 (heads hg*4+j), eidx = tid>>2 (8 floats)
// Phase B thread: hg2 = tid>>8 (8 heads), e4 = tid&255 (4 floats) -> 2x replication
// dyn smem: sx[2][RPB][1024] 128KB + spart[16][SPR] ~70KB
__global__ void __launch_bounds__(512, 1) k_fused(const float* __restrict__ seq2,
                                                  const int* __restrict__ mask) {
    extern __shared__ __align__(16) char dyn[];
    float* sx = (float*)dyn;                      // [2][16][1024]
    float* spart = (float*)(dyn + 131072);        // idx = r*SPR + h*68 + e2
    __shared__ __align__(16) u64 swp[RPB][H_];    // (w,w) pairs per row/head
    __shared__ __align__(16) u64 sfacp[H_];       // (fac,fac) per head
    __shared__ float sm_m[H_], sm_d[H_];
    __shared__ uint32_t sball[4];

    int b = blockIdx.y;
    int chunk = blockIdx.x;
    int s0 = chunk * CH;
    int tid = threadIdx.x;
    int hg = tid & 3;
    int eidx = tid >> 2;            // 0..127 (Phase A)
    int hg2 = tid >> 8;             // 0..1   (Phase B)
    int e4 = tid & 255;             // 0..255 (Phase B)

    if (tid < CH) {
        int mm = mask[b * S_ + s0 + tid];
        uint32_t bal = __ballot_sync(0xffffffffu, mm != 0);
        if ((tid & 31) == 0) sball[tid >> 5] = bal;
    }
    if (tid < H_) { sm_m[tid] = -1e30f; sm_d[tid] = 0.f; }

    // qk regs (Phase A): 4 heads x 8 e-floats
    u64 qk2[4][4];
#pragma unroll
    for (int j = 0; j < 4; j++) {
        const float4* p = (const float4*)(g_qk + ((size_t)b * H_ + hg * 4 + j) * E_ + eidx * 8);
        float4 v0 = p[0], v1 = p[1];
        qk2[j][0] = pack2(v0.x, v0.y);
        qk2[j][1] = pack2(v0.z, v0.w);
        qk2[j][2] = pack2(v1.x, v1.y);
        qk2[j][3] = pack2(v1.z, v1.w);
    }

    // ctx regs (Phase B): 8 heads x 4 floats -> per head 2 u64 (e0e1, e2e3)
    u64 ctx[8][2];
#pragma unroll
    for (int k = 0; k < 8; k++) {
        ctx[k][0] = pack2(0.f, 0.f);
        ctx[k][1] = pack2(0.f, 0.f);
    }

    uint32_t sx_addr = (uint32_t)__cvta_generic_to_shared(sx);
    const float* base = seq2 + ((size_t)b * S_ + s0) * E_;
    int r0 = tid >> 6;              // 0..7 staging row base
    int scol = tid & 63;            // 64 threads per row, 16 floats each

    __syncthreads();                // sball/sm_* visible

    // ---- staging: batch nb (16 rows) -> slot nb&1 ----
    auto stage = [&](int nb) {
        uint32_t flN = (sball[nb >> 1] >> ((nb & 1) * 16)) & 0xFFFFu;
        uint32_t slotOff = (uint32_t)(nb & 1) * 65536u;
#pragma unroll
        for (int h2 = 0; h2 < 2; h2++) {
            int row = h2 * 8 + r0;
            if ((flN >> row) & 1) {
                const float* src = base + ((size_t)nb * RPB + row) * E_ + scol * 4;
                uint32_t dst = sx_addr + slotOff + (uint32_t)row * 4096 + scol * 16;
#pragma unroll
                for (int k = 0; k < 4; k++) cp16(dst + k * 1024, src + k * 256);
            }
        }
        cp_commit();
    };

    stage(0);
    stage(1);

    for (int bat = 0; bat < NBAT; bat++) {
        cp_wait<1>();
        __syncthreads();            // sync1: batch `bat` (slot bat&1) ready

        uint32_t fl = (sball[bat >> 1] >> ((bat & 1) * 16)) & 0xFFFFu;
        const float* xs = sx + (bat & 1) * (RPB * 1024);

        // ---- Phase A: per-head partial dots ----
#pragma unroll
        for (int r = 0; r < RPB; r++) {
            if ((fl >> r) & 1) {
                const float4* xr = (const float4*)(xs + r * 1024 + eidx * 8);
                float4 xa = xr[0], xb = xr[1];
                u64 x0 = pack2(xa.x, xa.y), x1 = pack2(xa.z, xa.w);
                u64 x2 = pack2(xb.x, xb.y), x3 = pack2(xb.z, xb.w);
                float part[4];
#pragma unroll
                for (int j = 0; j < 4; j++) {
                    u64 a = fmul2(qk2[j][0], x0);
                    a = ffma2(qk2[j][1], x1, a);
                    a = ffma2(qk2[j][2], x2, a);
                    a = ffma2(qk2[j][3], x3, a);
                    float ax, ay;
                    unpack2(a, ax, ay);
                    part[j] = ax + ay;
                }
#pragma unroll
                for (int j = 0; j < 4; j++)
                    part[j] += __shfl_xor_sync(0xffffffffu, part[j], 4);
                if ((tid & 4) == 0) {
                    int e2 = eidx >> 1;     // 0..63
#pragma unroll
                    for (int j = 0; j < 4; j++)
                        spart[r * SPR + (hg * 4 + j) * 68 + e2] = part[j];
                }
            }
        }
        __syncthreads();            // sync2: spart complete

        // ---- merged reduce + online softmax: warp w == head w ----
        {
            int h = tid >> 5;       // 0..15 head
            int l = tid & 31;
            int r = l & 15;         // row
            int q = l >> 4;         // half of the 64 partials
            const float4* pb = (const float4*)(spart + r * SPR + h * 68 + q * 32);
            float4 v0 = pb[0], v1 = pb[1], v2 = pb[2], v3 = pb[3];
            float4 v4 = pb[4], v5 = pb[5], v6 = pb[6], v7 = pb[7];
            float s = ((((v0.x + v0.y) + (v0.z + v0.w)) + ((v1.x + v1.y) + (v1.z + v1.w))) +
                       (((v2.x + v2.y) + (v2.z + v2.w)) + ((v3.x + v3.y) + (v3.z + v3.w)))) +
                      ((((v4.x + v4.y) + (v4.z + v4.w)) + ((v5.x + v5.y) + (v5.z + v5.w))) +
                       (((v6.x + v6.y) + (v6.z + v6.w)) + ((v7.x + v7.y) + (v7.z + v7.w))));
            s += __shfl_xor_sync(0xffffffffu, s, 16);      // full score(r,h)
            bool act = (fl >> r) & 1;
            float sv = act ? s : -1e30f;
            float m0 = sm_m[h];
            float t = sv;
            t = fmaxf(t, __shfl_xor_sync(0xffffffffu, t, 1));
            t = fmaxf(t, __shfl_xor_sync(0xffffffffu, t, 2));
            t = fmaxf(t, __shfl_xor_sync(0xffffffffu, t, 4));
            t = fmaxf(t, __shfl_xor_sync(0xffffffffu, t, 8));   // max over rows
            float nm = fmaxf(t, m0);
            float fac = exp2f((m0 - nm) * L2E);
            float wgt = act ? exp2f((s - nm) * L2E) : 0.f;
            float ws = wgt;
            ws += __shfl_xor_sync(0xffffffffu, ws, 1);
            ws += __shfl_xor_sync(0xffffffffu, ws, 2);
            ws += __shfl_xor_sync(0xffffffffu, ws, 4);
            ws += __shfl_xor_sync(0xffffffffu, ws, 8);
            if (l < 16) swp[r][h] = pack2(wgt, wgt);
            if (l == 0) {
                sfacp[h] = pack2(fac, fac);
                sm_m[h] = nm;
                sm_d[h] = fmaf(fac, sm_d[h], ws);
            }
        }
        __syncthreads();            // sync3: swp/sfacp ready

        // ---- Phase B: rescale + weighted accumulate (8 heads x 4 floats, 2x repl) ----
        {
            const ulonglong2* fp = (const ulonglong2*)&sfacp[hg2 * 8];
            ulonglong2 f01 = fp[0], f23 = fp[1], f45 = fp[2], f67 = fp[3];
            u64 fa[8] = {f01.x, f01.y, f23.x, f23.y, f45.x, f45.y, f67.x, f67.y};
#pragma unroll
            for (int k = 0; k < 8; k++) {
                ctx[k][0] = fmul2(ctx[k][0], fa[k]);
                ctx[k][1] = fmul2(ctx[k][1], fa[k]);
            }
#pragma unroll
            for (int r = 0; r < RPB; r++) {
                if (!((fl >> r) & 1)) continue;
                const ulonglong2* wp = (const ulonglong2*)&swp[r][hg2 * 8];
                ulonglong2 w01 = wp[0], w23 = wp[1], w45 = wp[2], w67 = wp[3];
                u64 wa[8] = {w01.x, w01.y, w23.x, w23.y, w45.x, w45.y, w67.x, w67.y};
                float4 xv = *(const float4*)(xs + r * 1024 + e4 * 4);
                u64 x01 = pack2(xv.x, xv.y), x23 = pack2(xv.z, xv.w);
#pragma unroll
                for (int k = 0; k < 8; k++) {
                    ctx[k][0] = ffma2(wa[k], x01, ctx[k][0]);
                    ctx[k][1] = ffma2(wa[k], x23, ctx[k][1]);
                }
            }
        }
        __syncthreads();            // sync4: slot (bat&1) fully consumed

        if (bat + 2 < NBAT) stage(bat + 2);
        else cp_commit();
    }

    // epilogue: unnormalized ctx + per-chunk (m, d)
#pragma unroll
    for (int k = 0; k < 8; k++) {
        float* dst = g_ctxp + (((size_t)chunk * B_ + b) * H_ + hg2 * 8 + k) * E_ + e4 * 4;
        float x0, y0, x1, y1;
        unpack2(ctx[k][0], x0, y0);
        unpack2(ctx[k][1], x1, y1);
        *(float4*)dst = make_float4(x0, y0, x1, y1);
    }
    if (tid < H_) {
        g_m[(chunk * B_ + b) * H_ + tid] = sm_m[tid];
        g_d[(chunk * B_ + b) * H_ + tid] = sm_d[tid];
    }
}

// ---------------- K4: weighted combine + out = ctx@Wv + bv (2 b per block) ----------------
// grid (16 h, 16 bg) block 256
__global__ void k_out(const float* __restrict__ Wv, const float* __restrict__ bv,
                      float* __restrict__ out) {
    int h = blockIdx.x;
    int b0 = blockIdx.y * 2;
    int tid = threadIdx.x;
    int n = tid & 63;
    int qq = tid >> 6;

    __shared__ __align__(16) float sc[2][E_];
    __shared__ float smd[2][2][NC];    // [bb][m/d][c]
    __shared__ float swt[2][NC];

    if (tid < 2 * 2 * NC) {
        int bb = tid >> 6, sel = (tid >> 5) & 1, c = tid & 31;
        smd[bb][sel][c] = (sel ? g_d : g_m)[(c * B_ + b0 + bb) * H_ + h];
    }
    __syncthreads();
    if (tid < 2) {
        int bb = tid;
        float M = -1e30f;
#pragma unroll
        for (int c = 0; c < NC; c++) M = fmaxf(M, smd[bb][0][c]);
        float Dn = 0.f;
        float t[NC];
#pragma unroll
        for (int c = 0; c < NC; c++) {
            float e = exp2f((smd[bb][0][c] - M) * L2E);
            t[c] = e;
            Dn = fmaf(e, smd[bb][1][c], Dn);
        }
        float invD = 1.0f / Dn;
#pragma unroll
        for (int c = 0; c < NC; c++) swt[bb][c] = t[c] * invD;
    }
    __syncthreads();

#pragma unroll
    for (int bb = 0; bb < 2; bb++) {
        float4 a = make_float4(0.f, 0.f, 0.f, 0.f);
#pragma unroll 8
        for (int c = 0; c < NC; c++) {
            float w = swt[bb][c];
            float4 v = ((const float4*)(g_ctxp + (((size_t)c * B_ + b0 + bb) * H_ + h) * E_))[tid];
            a.x = fmaf(w, v.x, a.x);
            a.y = fmaf(w, v.y, a.y);
            a.z = fmaf(w, v.z, a.z);
            a.w = fmaf(w, v.w, a.w);
        }
        ((float4*)sc[bb])[tid] = a;
    }
    __syncthreads();

    int c = h * D_ + n;
    float a0[4] = {0.f, 0.f, 0.f, 0.f};
    float a1[4] = {0.f, 0.f, 0.f, 0.f};
#pragma unroll 4
    for (int e = 0; e < 256; e += 4) {
#pragma unroll
        for (int i = 0; i < 4; i++) {
            float w = Wv[(size_t)(qq * 256 + e + i) * E_ + c];
            a0[i] = fmaf(sc[0][qq * 256 + e + i], w, a0[i]);
            a1[i] = fmaf(sc[1][qq * 256 + e + i], w, a1[i]);
        }
    }
    float acc0 = (a0[0] + a0[1]) + (a0[2] + a0[3]);
    float acc1 = (a1[0] + a1[1]) + (a1[2] + a1[3]);

    __shared__ float part[2][4][64];
    part[0][qq][n] = acc0;
    part[1][qq][n] = acc1;
    __syncthreads();
    if (tid < 128) {
        int bb = tid >> 6, nn = tid & 63;
        float s = (part[bb][0][nn] + part[bb][1][nn]) + (part[bb][2][nn] + part[bb][3][nn]);
        out[(size_t)(b0 + bb) * E_ + h * D_ + nn] = s + bv[h * D_ + nn];
    }
}

// ---------------- launch ----------------
extern "C" void kernel_launch(void* const* d_in, const int* in_sizes, int n_in,
                              void* d_out, int out_size) {
    const float* seq1 = (const float*)d_in[0];
    const float* seq2 = (const float*)d_in[1];
    const int*   mask = (const int*)d_in[2];
    const float* Wq   = (const float*)d_in[3];
    const float* bq   = (const float*)d_in[4];
    const float* Wk   = (const float*)d_in[5];
    // d_in[6] = bk dropped (softmax-invariant uniform shift)
    const float* Wv   = (const float*)d_in[7];
    const float* bv   = (const float*)d_in[8];
    float* out = (float*)d_out;

    const int dynBytes = 131072 + RPB * SPR * 4;   // 128KB ring + ~70KB spart
    cudaFuncSetAttribute(k_fused, cudaFuncAttributeMaxDynamicSharedMemorySize, dynBytes);

    k_qproj<<<dim3(4, B_), 256>>>(seq1, Wq, bq);
    k_qk<<<dim3(H_, 16), 256>>>(Wk);
    k_pad<<<1, 32>>>();
    k_fused<<<dim3(NC, B_), 512, dynBytes>>>(seq2, mask);
    k_out<<<dim3(H_, 16), 256>>>(Wv, bv, out);
}

// round 16
// speedup vs baseline: 1.3462x; 1.3462x over previous
#include <cuda_runtime.h>
#include <cstdint>
#include <cstddef>

#define B_ 32
#define S_ 4096
#define E_ 1024
#define H_ 16
#define D_ 64
#define NC 16            // chunks over s (256 rows each)
#define CH 256           // rows per chunk
#define RPB 16           // rows per batch
#define NBAT 16          // CH / RPB
#define ES 8             // e-splits for qproj
#define SPR 1092         // spart row stride (floats): conflict-free
#define L2E 1.4426950408889634f

// ---------------- static scratch ----------------
__device__ float g_qpart[ES][B_ * E_];                // qproj partials
__device__ float g_qk[B_ * H_ * E_];
__device__ float g_ctxp[(size_t)NC * B_ * H_ * E_];   // unnormalized ctx per chunk (32MB)
__device__ float g_m[NC * B_ * H_];
__device__ float g_d[NC * B_ * H_];

typedef unsigned long long u64;

__device__ __forceinline__ u64 pack2(float x, float y) {
    u64 p;
    asm("mov.b64 %0, {%1, %2};" : "=l"(p) : "f"(x), "f"(y));
    return p;
}
__device__ __forceinline__ void unpack2(u64 p, float& x, float& y) {
    asm("mov.b64 {%0, %1}, %2;" : "=f"(x), "=f"(y) : "l"(p));
}
__device__ __forceinline__ u64 ffma2(u64 a, u64 b, u64 c) {
    u64 d;
    asm("fma.rn.f32x2 %0, %1, %2, %3;" : "=l"(d) : "l"(a), "l"(b), "l"(c));
    return d;
}
__device__ __forceinline__ u64 fmul2(u64 a, u64 b) {
    u64 d;
    asm("mul.rn.f32x2 %0, %1, %2;" : "=l"(d) : "l"(a), "l"(b));
    return d;
}
__device__ __forceinline__ void cp16(uint32_t dst_smem, const void* src) {
    asm volatile("cp.async.cg.shared.global [%0], [%1], 16;" :: "r"(dst_smem), "l"(src));
}
__device__ __forceinline__ void cp_commit() { asm volatile("cp.async.commit_group;"); }
template <int N>
__device__ __forceinline__ void cp_wait() { asm volatile("cp.async.wait_group %0;" :: "n"(N)); }

// ---------------- K1: qproj partials (e-split x8) ----------------
// grid (4 jt, 32 b, 8 es) block 256: qpart[es][b][j] = Σ_{e in split} seq1[b][e]·Wq[e][j]
__global__ void k_qproj(const float* __restrict__ seq1, const float* __restrict__ Wq) {
    int b = blockIdx.y;
    int es = blockIdx.z;
    int j = blockIdx.x * 256 + threadIdx.x;
    int e0 = es * 128;
    __shared__ __align__(16) float s1[128];
    if (threadIdx.x < 32)
        ((float4*)s1)[threadIdx.x] = ((const float4*)(seq1 + (size_t)b * E_ + e0))[threadIdx.x];
    __syncthreads();
    float a[8] = {0.f, 0.f, 0.f, 0.f, 0.f, 0.f, 0.f, 0.f};
#pragma unroll 2
    for (int e = 0; e < 128; e += 8) {
#pragma unroll
        for (int i = 0; i < 8; i++)
            a[i] = fmaf(s1[e + i], Wq[(size_t)(e0 + e + i) * E_ + j], a[i]);
    }
    g_qpart[es][b * E_ + j] =
        ((a[0] + a[1]) + (a[2] + a[3])) + ((a[4] + a[5]) + (a[6] + a[7]));
}

// ---------------- K2: qk[b][h][e] = (Σ_d q[b][h*64+d]·Wk[e][h*64+d]) * 0.125 ----------------
// grid (16 h, 16 et) block 256; sums qproj partials + bq inline
__global__ void k_qk(const float* __restrict__ Wk, const float* __restrict__ bq) {
    int h = blockIdx.x;
    int e = blockIdx.y * 64 + (threadIdx.x & 63);
    int bg = threadIdx.x >> 6;
    __shared__ __align__(16) float2 sq[B_][D_ / 2];
    for (int i = threadIdx.x; i < B_ * (D_ / 2); i += 256) {
        int b = i >> 5, dp = i & 31;
        float2 acc = ((const float2*)(bq + h * D_))[dp];
#pragma unroll
        for (int es = 0; es < ES; es++) {
            float2 v = ((const float2*)(g_qpart[es] + b * E_ + h * D_))[dp];
            acc.x += v.x;
            acc.y += v.y;
        }
        sq[b][dp] = acc;
    }
    __syncthreads();
    float2 wk[D_ / 2];
    const float2* wrow = (const float2*)(Wk + (size_t)e * E_ + h * D_);
#pragma unroll
    for (int i = 0; i < D_ / 2; i++) wk[i] = wrow[i];
#pragma unroll
    for (int bb = 0; bb < 8; bb++) {
        int b = bg * 8 + bb;
        float ax = 0.f, ay = 0.f;
#pragma unroll
        for (int i = 0; i < D_ / 2; i++) {
            float2 qv = sq[b][i];
            ax = fmaf(wk[i].x, qv.x, ax);
            ay = fmaf(wk[i].y, qv.y, ay);
        }
        g_qk[(b * H_ + h) * E_ + e] = (ax + ay) * 0.125f;
    }
}

// ---------------- pad kernel (keeps ncu sample index on k_fused) ----------------
__global__ void k_pad() {}

// ---------------- K3: fused scores + online softmax + ctx ----------------
// grid (NC, B_) block 512
// Phase A thread: hg = tid&3 (heads hg*4+j), eidx = tid>>2 (8 floats)
// Phase B thread: hg2 = tid>>8 (8 heads), e4 = tid&255 (4 floats) -> 2x replication
// dyn smem: sx[2][RPB][1024] 128KB + spart[16][SPR] ~70KB
__global__ void __launch_bounds__(512, 1) k_fused(const float* __restrict__ seq2,
                                                  const int* __restrict__ mask) {
    extern __shared__ __align__(16) char dyn[];
    float* sx = (float*)dyn;                      // [2][16][1024]
    float* spart = (float*)(dyn + 131072);        // idx = r*SPR + h*68 + e2
    __shared__ __align__(16) u64 swp[RPB][H_];    // (w,w) pairs per row/head
    __shared__ __align__(16) u64 sfacp[H_];       // (fac,fac) per head
    __shared__ float sm_m[H_], sm_d[H_];
    __shared__ uint32_t sball[8];

    int b = blockIdx.y;
    int chunk = blockIdx.x;
    int s0 = chunk * CH;
    int tid = threadIdx.x;
    int hg = tid & 3;
    int eidx = tid >> 2;            // 0..127 (Phase A)
    int hg2 = tid >> 8;             // 0..1   (Phase B)
    int e4 = tid & 255;             // 0..255 (Phase B)

    if (tid < CH) {
        int mm = mask[b * S_ + s0 + tid];
        uint32_t bal = __ballot_sync(0xffffffffu, mm != 0);
        if ((tid & 31) == 0) sball[tid >> 5] = bal;
    }
    if (tid < H_) { sm_m[tid] = -1e30f; sm_d[tid] = 0.f; }

    // qk regs (Phase A): 4 heads x 8 e-floats
    u64 qk2[4][4];
#pragma unroll
    for (int j = 0; j < 4; j++) {
        const float4* p = (const float4*)(g_qk + ((size_t)b * H_ + hg * 4 + j) * E_ + eidx * 8);
        float4 v0 = p[0], v1 = p[1];
        qk2[j][0] = pack2(v0.x, v0.y);
        qk2[j][1] = pack2(v0.z, v0.w);
        qk2[j][2] = pack2(v1.x, v1.y);
        qk2[j][3] = pack2(v1.z, v1.w);
    }

    // ctx regs (Phase B): 8 heads x 4 floats
    u64 ctx[8][2];
#pragma unroll
    for (int k = 0; k < 8; k++) {
        ctx[k][0] = pack2(0.f, 0.f);
        ctx[k][1] = pack2(0.f, 0.f);
    }

    uint32_t sx_addr = (uint32_t)__cvta_generic_to_shared(sx);
    const float* base = seq2 + ((size_t)b * S_ + s0) * E_;
    int r0 = tid >> 6;              // 0..7 staging row base
    int scol = tid & 63;            // 64 threads per row, 16 floats each

    __syncthreads();                // sball/sm_* visible

    // ---- staging: batch nb (16 rows) -> slot nb&1 ----
    auto stage = [&](int nb) {
        uint32_t flN = (sball[nb >> 1] >> ((nb & 1) * 16)) & 0xFFFFu;
        uint32_t slotOff = (uint32_t)(nb & 1) * 65536u;
#pragma unroll
        for (int h2 = 0; h2 < 2; h2++) {
            int row = h2 * 8 + r0;
            if ((flN >> row) & 1) {
                const float* src = base + ((size_t)nb * RPB + row) * E_ + scol * 4;
                uint32_t dst = sx_addr + slotOff + (uint32_t)row * 4096 + scol * 16;
#pragma unroll
                for (int k = 0; k < 4; k++) cp16(dst + k * 1024, src + k * 256);
            }
        }
        cp_commit();
    };

    stage(0);
    stage(1);

    for (int bat = 0; bat < NBAT; bat++) {
        cp_wait<1>();
        __syncthreads();            // sync1: batch `bat` (slot bat&1) ready

        uint32_t fl = (sball[bat >> 1] >> ((bat & 1) * 16)) & 0xFFFFu;
        const float* xs = sx + (bat & 1) * (RPB * 1024);

        // ---- Phase A: per-head partial dots ----
#pragma unroll
        for (int r = 0; r < RPB; r++) {
            if ((fl >> r) & 1) {
                const float4* xr = (const float4*)(xs + r * 1024 + eidx * 8);
                float4 xa = xr[0], xb = xr[1];
                u64 x0 = pack2(xa.x, xa.y), x1 = pack2(xa.z, xa.w);
                u64 x2 = pack2(xb.x, xb.y), x3 = pack2(xb.z, xb.w);
                float part[4];
#pragma unroll
                for (int j = 0; j < 4; j++) {
                    u64 a = fmul2(qk2[j][0], x0);
                    a = ffma2(qk2[j][1], x1, a);
                    a = ffma2(qk2[j][2], x2, a);
                    a = ffma2(qk2[j][3], x3, a);
                    float ax, ay;
                    unpack2(a, ax, ay);
                    part[j] = ax + ay;
                }
#pragma unroll
                for (int j = 0; j < 4; j++)
                    part[j] += __shfl_xor_sync(0xffffffffu, part[j], 4);
                if ((tid & 4) == 0) {
                    int e2 = eidx >> 1;     // 0..63
#pragma unroll
                    for (int j = 0; j < 4; j++)
                        spart[r * SPR + (hg * 4 + j) * 68 + e2] = part[j];
                }
            }
        }
        __syncthreads();            // sync2: spart complete

        // ---- merged reduce + online softmax: warp w == head w ----
        {
            int h = tid >> 5;       // 0..15 head
            int l = tid & 31;
            int r = l & 15;         // row
            int q = l >> 4;         // half of the 64 partials
            const float4* pb = (const float4*)(spart + r * SPR + h * 68 + q * 32);
            float4 v0 = pb[0], v1 = pb[1], v2 = pb[2], v3 = pb[3];
            float4 v4 = pb[4], v5 = pb[5], v6 = pb[6], v7 = pb[7];
            float s = ((((v0.x + v0.y) + (v0.z + v0.w)) + ((v1.x + v1.y) + (v1.z + v1.w))) +
                       (((v2.x + v2.y) + (v2.z + v2.w)) + ((v3.x + v3.y) + (v3.z + v3.w)))) +
                      ((((v4.x + v4.y) + (v4.z + v4.w)) + ((v5.x + v5.y) + (v5.z + v5.w))) +
                       (((v6.x + v6.y) + (v6.z + v6.w)) + ((v7.x + v7.y) + (v7.z + v7.w))));
            s += __shfl_xor_sync(0xffffffffu, s, 16);      // full score(r,h)
            bool act = (fl >> r) & 1;
            float sv = act ? s : -1e30f;
            float m0 = sm_m[h];
            float t = sv;
            t = fmaxf(t, __shfl_xor_sync(0xffffffffu, t, 1));
            t = fmaxf(t, __shfl_xor_sync(0xffffffffu, t, 2));
            t = fmaxf(t, __shfl_xor_sync(0xffffffffu, t, 4));
            t = fmaxf(t, __shfl_xor_sync(0xffffffffu, t, 8));   // max over rows
            float nm = fmaxf(t, m0);
            float fac = exp2f((m0 - nm) * L2E);
            float wgt = act ? exp2f((s - nm) * L2E) : 0.f;
            float ws = wgt;
            ws += __shfl_xor_sync(0xffffffffu, ws, 1);
            ws += __shfl_xor_sync(0xffffffffu, ws, 2);
            ws += __shfl_xor_sync(0xffffffffu, ws, 4);
            ws += __shfl_xor_sync(0xffffffffu, ws, 8);
            if (l < 16) swp[r][h] = pack2(wgt, wgt);
            if (l == 0) {
                sfacp[h] = pack2(fac, fac);
                sm_m[h] = nm;
                sm_d[h] = fmaf(fac, sm_d[h], ws);
            }
        }
        __syncthreads();            // sync3: swp/sfacp ready

        // ---- Phase B: rescale + weighted accumulate (8 heads x 4 floats, 2x repl) ----
        {
            const ulonglong2* fp = (const ulonglong2*)&sfacp[hg2 * 8];
            ulonglong2 f01 = fp[0], f23 = fp[1], f45 = fp[2], f67 = fp[3];
            u64 fa[8] = {f01.x, f01.y, f23.x, f23.y, f45.x, f45.y, f67.x, f67.y};
#pragma unroll
            for (int k = 0; k < 8; k++) {
                ctx[k][0] = fmul2(ctx[k][0], fa[k]);
                ctx[k][1] = fmul2(ctx[k][1], fa[k]);
            }
#pragma unroll
            for (int r = 0; r < RPB; r++) {
                if (!((fl >> r) & 1)) continue;
                const ulonglong2* wp = (const ulonglong2*)&swp[r][hg2 * 8];
                ulonglong2 w01 = wp[0], w23 = wp[1], w45 = wp[2], w67 = wp[3];
                u64 wa[8] = {w01.x, w01.y, w23.x, w23.y, w45.x, w45.y, w67.x, w67.y};
                float4 xv = *(const float4*)(xs + r * 1024 + e4 * 4);
                u64 x01 = pack2(xv.x, xv.y), x23 = pack2(xv.z, xv.w);
#pragma unroll
                for (int k = 0; k < 8; k++) {
                    ctx[k][0] = ffma2(wa[k], x01, ctx[k][0]);
                    ctx[k][1] = ffma2(wa[k], x23, ctx[k][1]);
                }
            }
        }
        __syncthreads();            // sync4: slot (bat&1) fully consumed

        if (bat + 2 < NBAT) stage(bat + 2);
        else cp_commit();
    }

    // epilogue: unnormalized ctx + per-chunk (m, d)
#pragma unroll
    for (int k = 0; k < 8; k++) {
        float* dst = g_ctxp + (((size_t)chunk * B_ + b) * H_ + hg2 * 8 + k) * E_ + e4 * 4;
        float x0, y0, x1, y1;
        unpack2(ctx[k][0], x0, y0);
        unpack2(ctx[k][1], x1, y1);
        *(float4*)dst = make_float4(x0, y0, x1, y1);
    }
    if (tid < H_) {
        g_m[(chunk * B_ + b) * H_ + tid] = sm_m[tid];
        g_d[(chunk * B_ + b) * H_ + tid] = sm_d[tid];
    }
}

// ---------------- K4: weighted combine + out = ctx@Wv + bv (2 b per block) ----------------
// grid (16 h, 16 bg) block 256
__global__ void k_out(const float* __restrict__ Wv, const float* __restrict__ bv,
                      float* __restrict__ out) {
    int h = blockIdx.x;
    int b0 = blockIdx.y * 2;
    int tid = threadIdx.x;
    int n = tid & 63;
    int qq = tid >> 6;

    __shared__ __align__(16) float sc[2][E_];
    __shared__ float smd[2][2][NC];    // [bb][m/d][c]
    __shared__ float swt[2][NC];

    if (tid < 2 * 2 * NC) {
        int bb = tid >> 5, sel = (tid >> 4) & 1, c = tid & 15;
        smd[bb][sel][c] = (sel ? g_d : g_m)[(c * B_ + b0 + bb) * H_ + h];
    }
    __syncthreads();
    if (tid < 2) {
        int bb = tid;
        float M = -1e30f;
#pragma unroll
        for (int c = 0; c < NC; c++) M = fmaxf(M, smd[bb][0][c]);
        float Dn = 0.f;
        float t[NC];
#pragma unroll
        for (int c = 0; c < NC; c++) {
            float e = exp2f((smd[bb][0][c] - M) * L2E);
            t[c] = e;
            Dn = fmaf(e, smd[bb][1][c], Dn);
        }
        float invD = 1.0f / Dn;
#pragma unroll
        for (int c = 0; c < NC; c++) swt[bb][c] = t[c] * invD;
    }
    __syncthreads();

#pragma unroll
    for (int bb = 0; bb < 2; bb++) {
        float4 a = make_float4(0.f, 0.f, 0.f, 0.f);
#pragma unroll 8
        for (int c = 0; c < NC; c++) {
            float w = swt[bb][c];
            float4 v = ((const float4*)(g_ctxp + (((size_t)c * B_ + b0 + bb) * H_ + h) * E_))[tid];
            a.x = fmaf(w, v.x, a.x);
            a.y = fmaf(w, v.y, a.y);
            a.z = fmaf(w, v.z, a.z);
            a.w = fmaf(w, v.w, a.w);
        }
        ((float4*)sc[bb])[tid] = a;
    }
    __syncthreads();

    int c = h * D_ + n;
    float a0[4] = {0.f, 0.f, 0.f, 0.f};
    float a1[4] = {0.f, 0.f, 0.f, 0.f};
#pragma unroll 4
    for (int e = 0; e < 256; e += 4) {
#pragma unroll
        for (int i = 0; i < 4; i++) {
            float w = Wv[(size_t)(qq * 256 + e + i) * E_ + c];
            a0[i] = fmaf(sc[0][qq * 256 + e + i], w, a0[i]);
            a1[i] = fmaf(sc[1][qq * 256 + e + i], w, a1[i]);
        }
    }
    float acc0 = (a0[0] + a0[1]) + (a0[2] + a0[3]);
    float acc1 = (a1[0] + a1[1]) + (a1[2] + a1[3]);

    __shared__ float part[2][4][64];
    part[0][qq][n] = acc0;
    part[1][qq][n] = acc1;
    __syncthreads();
    if (tid < 128) {
        int bb = tid >> 6, nn = tid & 63;
        float s = (part[bb][0][nn] + part[bb][1][nn]) + (part[bb][2][nn] + part[bb][3][nn]);
        out[(size_t)(b0 + bb) * E_ + h * D_ + nn] = s + bv[h * D_ + nn];
    }
}

// ---------------- launch ----------------
extern "C" void kernel_launch(void* const* d_in, const int* in_sizes, int n_in,
                              void* d_out, int out_size) {
    const float* seq1 = (const float*)d_in[0];
    const float* seq2 = (const float*)d_in[1];
    const int*   mask = (const int*)d_in[2];
    const float* Wq   = (const float*)d_in[3];
    const float* bq   = (const float*)d_in[4];
    const float* Wk   = (const float*)d_in[5];
    // d_in[6] = bk dropped (softmax-invariant uniform shift)
    const float* Wv   = (const float*)d_in[7];
    const float* bv   = (const float*)d_in[8];
    float* out = (float*)d_out;

    const int dynBytes = 131072 + RPB * SPR * 4;   // 128KB ring + ~70KB spart
    cudaFuncSetAttribute(k_fused, cudaFuncAttributeMaxDynamicSharedMemorySize, dynBytes);

    k_qproj<<<dim3(4, B_, ES), 256>>>(seq1, Wq);
    k_qk<<<dim3(H_, 16), 256>>>(Wk, bq);
    k_pad<<<1, 32>>>();
    k_fused<<<dim3(NC, B_), 512, dynBytes>>>(seq2, mask);
    k_out<<<dim3(H_, 16), 256>>>(Wv, bv, out);
}